// round 1
// baseline (speedup 1.0000x reference)
#include <cuda_runtime.h>
#include <cstdint>

// Shapes fixed by the problem: x is (64, 128, 4096) fp32.
#define NPOS   4096
#define NROWS  8192          // 64*128
#define NTILES 33            // ceil coverage of centers 1..4094 with step-124 tiles
#define NSTRIP 32            // 8192 rows / 256 rows-per-strip

// Scratch in __device__ globals (no allocations allowed).
__device__ unsigned int g_counts[NPOS];   // packed: peak in low16, valley in high16
__device__ float        g_vec[NPOS];
__device__ float        g_norm[NPOS];

// ---------------------------------------------------------------------------
// K0: zero the packed count array (graph is replayed; must be idempotent)
// ---------------------------------------------------------------------------
__global__ void k_zero() {
    int i = blockIdx.x * blockDim.x + threadIdx.x;
    if (i < NPOS) g_counts[i] = 0u;
}

// ---------------------------------------------------------------------------
// K1: count peaks/valleys per column position.
// Each warp owns a 128-float column tile (float4 per lane), iterates 32 rows,
// accumulates packed counts in registers, then flushes 4 atomics per lane.
// dd is computed exactly like the reference: (x[p+1]-x[p]) - (x[p]-x[p-1]).
// ---------------------------------------------------------------------------
__global__ __launch_bounds__(256) void k_counts(const float* __restrict__ x) {
    const int lane = threadIdx.x & 31;
    const int warp = threadIdx.x >> 5;          // 0..7
    const int tile = blockIdx.x;                // 0..32
    const int s    = tile * 124;                // tile covers x columns [s, s+128)
    // Centers this tile is responsible for: [s+1, cmax] (disjoint across tiles)
    const int cmax = (tile == NTILES - 1) ? (NPOS - 2) : (s + 124);
    const int p0   = s + 4 * lane + 1;

    const unsigned m0 = (p0 + 0 <= cmax) ? 0xFFFFFFFFu : 0u;
    const unsigned m1 = (p0 + 1 <= cmax) ? 0xFFFFFFFFu : 0u;
    const unsigned m2 = (p0 + 2 <= cmax) ? 0xFFFFFFFFu : 0u;
    const unsigned m3 = (p0 + 3 <= cmax) ? 0xFFFFFFFFu : 0u;

    unsigned acc0 = 0, acc1 = 0, acc2 = 0, acc3 = 0;

    const int rowbase = blockIdx.y * 256 + warp * 32;
    const float* xb = x + (size_t)rowbase * NPOS + s;

    #pragma unroll 4
    for (int k = 0; k < 32; k++) {
        float4 v = __ldg((const float4*)(xb + (size_t)k * NPOS) + lane);
        // Seam values from the next lane (garbage in lane 31, but lane 31's
        // dependent centers are always masked out by m2/m3).
        float xn0 = __shfl_down_sync(0xFFFFFFFFu, v.x, 1);
        float xn1 = __shfl_down_sync(0xFFFFFFFFu, v.y, 1);

        float d0 = v.y - v.x;
        float d1 = v.z - v.y;
        float d2 = v.w - v.z;
        float d3 = xn0 - v.w;
        float d4 = xn1 - xn0;

        float dd0 = d1 - d0;   // center p0
        float dd1 = d2 - d1;   // center p0+1
        float dd2 = d3 - d2;   // center p0+2
        float dd3 = d4 - d3;   // center p0+3

        acc0 += m0 & (((unsigned)(dd0 < 0.0f)) | (((unsigned)(dd0 > 0.0f)) << 16));
        acc1 += m1 & (((unsigned)(dd1 < 0.0f)) | (((unsigned)(dd1 > 0.0f)) << 16));
        acc2 += m2 & (((unsigned)(dd2 < 0.0f)) | (((unsigned)(dd2 > 0.0f)) << 16));
        acc3 += m3 & (((unsigned)(dd3 < 0.0f)) | (((unsigned)(dd3 > 0.0f)) << 16));
    }

    if (m0) atomicAdd(&g_counts[p0 + 0], acc0);
    if (m1) atomicAdd(&g_counts[p0 + 1], acc1);
    if (m2) atomicAdd(&g_counts[p0 + 2], acc2);
    if (m3) atomicAdd(&g_counts[p0 + 3], acc3);
}

// ---------------------------------------------------------------------------
// K2: gaussian convolution of counts -> g_vec.
// Tail beyond radius R = 9*w is < exp(-81) ~ 6e-36: exactly 0 in fp32 terms.
// ---------------------------------------------------------------------------
__global__ __launch_bounds__(128) void k_vec(const float* __restrict__ lpw,
                                             const float* __restrict__ lvw) {
    __shared__ float sgp[NPOS];
    __shared__ float sgv[NPOS];

    const float wp = expf(*lpw);
    const float wv = expf(*lvw);
    int R = (int)(9.0f * fmaxf(wp, wv)) + 1;
    if (R > NPOS - 1) R = NPOS - 1;

    for (int d = threadIdx.x; d <= R; d += blockDim.x) {
        float fd = (float)d;
        float tp = fd / wp;
        float tv = fd / wv;
        sgp[d] = expf(-tp * tp);
        sgv[d] = expf(-tv * tv);
    }
    __syncthreads();

    const int p = blockIdx.x * blockDim.x + threadIdx.x;
    float acc = 0.0f;
    for (int d = -R; d <= R; d++) {
        int c = p - d;
        if ((unsigned)c < (unsigned)NPOS) {
            unsigned pk = g_counts[c];
            int ad = d < 0 ? -d : d;
            acc += (float)(pk & 0xFFFFu) * sgp[ad]
                 + (float)(pk >> 16)     * sgv[ad];
        }
    }
    g_vec[p] = acc;
}

// ---------------------------------------------------------------------------
// K3: min/max over g_vec + normalize into g_norm. Single block.
// ---------------------------------------------------------------------------
__global__ __launch_bounds__(1024) void k_norm() {
    __shared__ float smn[32], smx[32];
    const int t = threadIdx.x;

    float mn =  3.402823e38f;
    float mx = -3.402823e38f;
    for (int i = t; i < NPOS; i += 1024) {
        float v = g_vec[i];
        mn = fminf(mn, v);
        mx = fmaxf(mx, v);
    }
    #pragma unroll
    for (int o = 16; o > 0; o >>= 1) {
        mn = fminf(mn, __shfl_xor_sync(0xFFFFFFFFu, mn, o));
        mx = fmaxf(mx, __shfl_xor_sync(0xFFFFFFFFu, mx, o));
    }
    if ((t & 31) == 0) { smn[t >> 5] = mn; smx[t >> 5] = mx; }
    __syncthreads();
    if (t < 32) {
        mn = smn[t]; mx = smx[t];
        #pragma unroll
        for (int o = 16; o > 0; o >>= 1) {
            mn = fminf(mn, __shfl_xor_sync(0xFFFFFFFFu, mn, o));
            mx = fmaxf(mx, __shfl_xor_sync(0xFFFFFFFFu, mx, o));
        }
        if (t == 0) { smn[0] = mn; smx[0] = mx; }
    }
    __syncthreads();
    mn = smn[0];
    mx = smx[0];
    const float denom = mx - mn + 1e-6f;
    for (int i = t; i < NPOS; i += 1024) {
        g_norm[i] = (g_vec[i] - mn) / denom;
    }
}

// ---------------------------------------------------------------------------
// K4: broadcast normalized vector to all 8192 rows of the output.
// Block = 1024 threads (one float4 column-group each); 16 rows per block.
// ---------------------------------------------------------------------------
__global__ __launch_bounds__(1024) void k_bcast(float* __restrict__ out) {
    const int t = threadIdx.x;
    const float4 v = ((const float4*)g_norm)[t];
    float4* o = (float4*)out + (size_t)blockIdx.x * 16 * 1024 + t;
    #pragma unroll
    for (int r = 0; r < 16; r++) {
        o[(size_t)r * 1024] = v;
    }
}

// ---------------------------------------------------------------------------
extern "C" void kernel_launch(void* const* d_in, const int* in_sizes, int n_in,
                              void* d_out, int out_size) {
    const float* x   = (const float*)d_in[0];
    const float* lpw = (const float*)d_in[1];
    const float* lvw = (const float*)d_in[2];
    float* out = (float*)d_out;

    k_zero<<<(NPOS + 255) / 256, 256>>>();
    k_counts<<<dim3(NTILES, NSTRIP), 256>>>(x);
    k_vec<<<NPOS / 128, 128>>>(lpw, lvw);
    k_norm<<<1, 1024>>>();
    k_bcast<<<NROWS / 16, 1024>>>(out);
}